// round 9
// baseline (speedup 1.0000x reference)
#include <cuda_runtime.h>

#define NN 50000
#define NE 800000
#define C  128
#define NG 128
#define OC 16
#define NBLK 196   // ceil(50000/256)

// Scratch (static device globals — no allocation in kernel_launch)
__device__ __align__(16) float g_A[NN * C];     // hs = (X@W)*dis  (layer output pre-agg)
__device__ __align__(16) float g_X2[NN * C];    // layer-2 input
__device__ __align__(16) float g_pool[NG * C];
__device__ float g_dis[NN];
__device__ int   g_src[NE];
__device__ int   g_dst[NE];
__device__ int   g_bat[NN];
__device__ int   g_cnt_i[NN];    // in-degree histogram (by dst)
__device__ int   g_cursor[NN];   // fill cursors
__device__ int   g_rs[NN + 1];   // CSR row starts
__device__ int   g_col[NE];      // CSR column (src) ids
__device__ int   g_gcnt[NG];     // nodes per graph
__device__ int   g_bsum[NBLK];   // per-block degree sums
__device__ int   g_boff[NBLK];   // per-block scan offsets
__device__ int   g_done;         // scanA completion counter
__device__ int   g_is64;

// launch 0: zero counters + dtype detect (thread 0)
__global__ void k_init(const int* __restrict__ ei_raw) {
    int i = blockIdx.x * blockDim.x + threadIdx.x;
    if (i == 0) {
        int hi_or = 0, lo_ok = 1;
        for (int j = 0; j < 256; j++) {
            hi_or |= ei_raw[2 * j + 1];
            int lo = ei_raw[2 * j];
            lo_ok &= (lo >= 0 && lo < NN) ? 1 : 0;
        }
        g_is64 = (hi_or == 0 && lo_ok) ? 1 : 0;
        g_done = 0;
    }
    if (i < NN) g_cnt_i[i] = 0;
    if (i < NG * C) g_pool[i] = 0.0f;
    if (i < NG) g_gcnt[i] = 0;
}

// launch 1: dtype-normalize + in-degree histogram + per-graph node counts
__global__ void k_convert_hist(const void* __restrict__ ei_raw, const void* __restrict__ bat_raw) {
    int i = blockIdx.x * blockDim.x + threadIdx.x;
    const bool is64 = (g_is64 != 0);
    if (i < NE) {
        int s, d;
        if (is64) {
            const long long* p = (const long long*)ei_raw;
            s = (int)p[i]; d = (int)p[NE + i];
        } else {
            const int* p = (const int*)ei_raw;
            s = p[i]; d = p[NE + i];
        }
        g_src[i] = s; g_dst[i] = d;
        atomicAdd(&g_cnt_i[d], 1);
    }
    if (i < NN) {
        int b = is64 ? (int)((const long long*)bat_raw)[i] : ((const int*)bat_raw)[i];
        g_bat[i] = b;
        atomicAdd(&g_gcnt[b], 1);
    }
}

// launch 2: dis = rsqrt(deg+1), per-block sums, last-done block scans block sums
__global__ void k_scanA() {
    int t = threadIdx.x;
    int i = blockIdx.x * blockDim.x + t;
    int c = (i < NN) ? g_cnt_i[i] : 0;
    if (i < NN) g_dis[i] = rsqrtf((float)(c + 1));

    int r = c;
#pragma unroll
    for (int off = 16; off > 0; off >>= 1)
        r += __shfl_down_sync(0xffffffffu, r, off);
    __shared__ int ws[8];
    int lane = t & 31, w = t >> 5;
    if (lane == 0) ws[w] = r;
    __syncthreads();
    __shared__ int isLast;
    if (t == 0) {
        int s = 0;
#pragma unroll
        for (int j = 0; j < 8; j++) s += ws[j];
        g_bsum[blockIdx.x] = s;
        __threadfence();
        int v = atomicAdd(&g_done, 1);
        isLast = (v == gridDim.x - 1) ? 1 : 0;
    }
    __syncthreads();
    if (isLast) {
        __shared__ int s[256];
        int v = (t < NBLK) ? g_bsum[t] : 0;
        s[t] = v;
        __syncthreads();
#pragma unroll
        for (int off = 1; off < 256; off <<= 1) {
            int x = (t >= off) ? s[t - off] : 0;
            __syncthreads();
            s[t] += x;
            __syncthreads();
        }
        if (t < NBLK) g_boff[t] = s[t] - v;
    }
}

// launches 3,7: out = (X @ W) * dis[row].  BM=64 rows/block, 256 threads.
// k-pair packed FFMA2: acc lanes hold even-k / odd-k partial sums.
//   smem Wp[kp][col] = {W[2kp][col], W[2kp+1][col]}   (64 x 128 float2, 64KB)
//   smem Xs[row][k]  row-major floats                 (64 x 128, 32KB)
// Thread (tx,ty): rows ty*8..ty*8+7, cols tx+32j (j=0..3).
__global__ __launch_bounds__(256) void k_gemm(
        const float* __restrict__ X, const float* __restrict__ W,
        const float* __restrict__ dis, float* __restrict__ out) {
    extern __shared__ float sm[];
    float2* Wp = (float2*)sm;              // 8192 float2 = 64KB
    float*  Xs = sm + 2 * 8192;            // 8192 floats = 32KB
    const unsigned long long* Wp8 = (const unsigned long long*)Wp;
    const int tid = threadIdx.x;
    const int bm = blockIdx.x * 64;

    // Stage W as k-pairs: iterate 2048 (kp, c4) units; each makes 8 paired floats.
#pragma unroll
    for (int t = 0; t < 8; t++) {
        int idx = tid + t * 256;           // 0..2047
        int kp = idx >> 5, c4 = idx & 31;  // kp row-pair, c4 = float4 group
        float4 a = ((const float4*)W)[(2 * kp) * 32 + c4];
        float4 b = ((const float4*)W)[(2 * kp + 1) * 32 + c4];
        float4* dstp = (float4*)&Wp[kp * 128 + c4 * 4];
        dstp[0] = make_float4(a.x, b.x, a.y, b.y);
        dstp[1] = make_float4(a.z, b.z, a.w, b.w);
    }
    // Stage X tile (64 rows x 128 cols)
#pragma unroll
    for (int t = 0; t < 8; t++) {
        int idx = tid + t * 256;
        int row = idx >> 5, c4 = idx & 31;
        int gr = bm + row;
        float4 v = make_float4(0.f, 0.f, 0.f, 0.f);
        if (gr < NN) v = ((const float4*)X)[gr * 32 + c4];
        ((float4*)Xs)[idx] = v;
    }
    __syncthreads();

    const int tx = tid & 31;
    const int ty = tid >> 5;

    unsigned long long acc2[8][4];
#pragma unroll
    for (int i = 0; i < 8; i++)
#pragma unroll
        for (int j = 0; j < 4; j++) acc2[i][j] = 0ULL;

#pragma unroll 4
    for (int kp = 0; kp < 64; kp++) {
        unsigned long long a2[8];
#pragma unroll
        for (int i = 0; i < 8; i++)   // warp-uniform broadcast LDS.64
            a2[i] = *(const unsigned long long*)(Xs + (ty * 8 + i) * 128 + 2 * kp);
        unsigned long long b2[4];
#pragma unroll
        for (int j = 0; j < 4; j++)   // stride-2-word, conflict-free LDS.64
            b2[j] = Wp8[kp * 128 + tx + 32 * j];
#pragma unroll
        for (int i = 0; i < 8; i++) {
#pragma unroll
            for (int j = 0; j < 4; j++) {
                asm("fma.rn.f32x2 %0, %1, %2, %0;"
                    : "+l"(acc2[i][j]) : "l"(a2[i]), "l"(b2[j]));
            }
        }
    }

#pragma unroll
    for (int i = 0; i < 8; i++) {
        int r = bm + ty * 8 + i;
        if (r < NN) {
            float s = dis[r];
#pragma unroll
            for (int j = 0; j < 4; j++) {
                unsigned int lo, hi;
                asm("mov.b64 {%0, %1}, %2;" : "=r"(lo), "=r"(hi) : "l"(acc2[i][j]));
                out[r * C + tx + 32 * j] =
                    (__uint_as_float(lo) + __uint_as_float(hi)) * s;
            }
        }
    }
}

// launch 4: per-element exclusive scan + write rs/cursor
__global__ void k_scanB() {
    int t = threadIdx.x;
    int i = blockIdx.x * blockDim.x + t;
    int c = (i < NN) ? g_cnt_i[i] : 0;
    int lane = t & 31, w = t >> 5;
    int incl = c;
#pragma unroll
    for (int off = 1; off < 32; off <<= 1) {
        int n = __shfl_up_sync(0xffffffffu, incl, off);
        if (lane >= off) incl += n;
    }
    __shared__ int wsum[8], woff[8];
    if (lane == 31) wsum[w] = incl;
    __syncthreads();
    if (t == 0) {
        int run = 0;
#pragma unroll
        for (int j = 0; j < 8; j++) { woff[j] = run; run += wsum[j]; }
    }
    __syncthreads();
    if (i < NN) {
        int pre = (incl - c) + woff[w] + g_boff[blockIdx.x];
        g_rs[i] = pre;
        g_cursor[i] = pre;
    }
    if (i == 0) g_rs[NN] = NE;
}

// launch 5: CSR fill
__global__ void k_fill() {
    int e = blockIdx.x * blockDim.x + threadIdx.x;
    if (e < NE) {
        int d = g_dst[e];
        int off = atomicAdd(&g_cursor[d], 1);
        g_col[off] = g_src[e];
    }
}

// gather core: acc = hs[d] (self loop) + sum_{e in row d} hs[col[e]], 4-way unrolled
__device__ __forceinline__ float4 agg_row(const float4* __restrict__ hs4, int d, int lane) {
    float4 acc = hs4[d * 32 + lane];
    int e = g_rs[d], end = g_rs[d + 1];
    for (; e + 4 <= end; e += 4) {
        int s0 = g_col[e], s1 = g_col[e + 1], s2 = g_col[e + 2], s3 = g_col[e + 3];
        float4 v0 = hs4[s0 * 32 + lane];
        float4 v1 = hs4[s1 * 32 + lane];
        float4 v2 = hs4[s2 * 32 + lane];
        float4 v3 = hs4[s3 * 32 + lane];
        acc.x += v0.x + v1.x + v2.x + v3.x;
        acc.y += v0.y + v1.y + v2.y + v3.y;
        acc.z += v0.z + v1.z + v2.z + v3.z;
        acc.w += v0.w + v1.w + v2.w + v3.w;
    }
    for (; e < end; e++) {
        int s = g_col[e];
        float4 v = hs4[s * 32 + lane];
        acc.x += v.x; acc.y += v.y; acc.z += v.z; acc.w += v.w;
    }
    return acc;
}

// launch 6: layer-1 aggregation + relu.  One warp per dst node.
__global__ void k_agg_relu(const float* __restrict__ hs, const float* __restrict__ bias,
                           float* __restrict__ out) {
    int d = blockIdx.x * (blockDim.x >> 5) + (threadIdx.x >> 5);
    int lane = threadIdx.x & 31;
    if (d >= NN) return;
    float4 acc = agg_row((const float4*)hs, d, lane);
    float sc = g_dis[d];
    float4 bb = ((const float4*)bias)[lane];
    float4 o;
    o.x = fmaxf(fmaf(sc, acc.x, bb.x), 0.f);
    o.y = fmaxf(fmaf(sc, acc.y, bb.y), 0.f);
    o.z = fmaxf(fmaf(sc, acc.z, bb.z), 0.f);
    o.w = fmaxf(fmaf(sc, acc.w, bb.w), 0.f);
    ((float4*)out)[d * 32 + lane] = o;
}

// launch 8: layer-2 aggregation + relu + mean-pool scatter
__global__ void k_agg_pool(const float* __restrict__ hs, const float* __restrict__ bias) {
    int d = blockIdx.x * (blockDim.x >> 5) + (threadIdx.x >> 5);
    int lane = threadIdx.x & 31;
    if (d >= NN) return;
    float4 acc = agg_row((const float4*)hs, d, lane);
    float sc = g_dis[d];
    float4 bb = ((const float4*)bias)[lane];
    float4 o;
    o.x = fmaxf(fmaf(sc, acc.x, bb.x), 0.f);
    o.y = fmaxf(fmaf(sc, acc.y, bb.y), 0.f);
    o.z = fmaxf(fmaf(sc, acc.z, bb.z), 0.f);
    o.w = fmaxf(fmaf(sc, acc.w, bb.w), 0.f);
    int g = g_bat[d];
    float* p = g_pool + g * C + lane * 4;
    atomicAdd(p + 0, o.x);
    atomicAdd(p + 1, o.y);
    atomicAdd(p + 2, o.z);
    atomicAdd(p + 3, o.w);
}

// launch 9: 128 threads, one graph per thread. FC + log_softmax.
__global__ void k_fc(const float* __restrict__ Wfc, const float* __restrict__ bfc,
                     float* __restrict__ out) {
    __shared__ float Wf[C * OC];
    int t = threadIdx.x;
    for (int i = t; i < C * OC; i += 128) Wf[i] = Wfc[i];
    __syncthreads();

    float inv = 1.0f / fmaxf((float)g_gcnt[t], 1.0f);
    float acc[OC];
#pragma unroll
    for (int j = 0; j < OC; j++) acc[j] = bfc[j];
    for (int k = 0; k < C; k++) {
        float p = g_pool[t * C + k] * inv;
#pragma unroll
        for (int j = 0; j < OC; j++) acc[j] += p * Wf[k * OC + j];
    }
    float m = acc[0];
#pragma unroll
    for (int j = 1; j < OC; j++) m = fmaxf(m, acc[j]);
    float sum = 0.f;
#pragma unroll
    for (int j = 0; j < OC; j++) sum += expf(acc[j] - m);
    float lse = m + logf(sum);
#pragma unroll
    for (int j = 0; j < OC; j++) out[t * OC + j] = acc[j] - lse;
}

extern "C" void kernel_launch(void* const* d_in, const int* in_sizes, int n_in,
                              void* d_out, int out_size) {
    const float* x     = (const float*)d_in[0];
    const void*  ei    = d_in[1];
    const void*  batch = d_in[2];
    const float* W1    = (const float*)d_in[3];
    const float* b1    = (const float*)d_in[4];
    const float* W2    = (const float*)d_in[5];
    const float* b2    = (const float*)d_in[6];
    const float* Wfc   = (const float*)d_in[7];
    const float* bfc   = (const float*)d_in[8];
    float* out = (float*)d_out;

    float *A, *X2, *dis;
    cudaGetSymbolAddress((void**)&A,   g_A);
    cudaGetSymbolAddress((void**)&X2,  g_X2);
    cudaGetSymbolAddress((void**)&dis, g_dis);

    size_t smem = (size_t)(64 * C + 64 * C) * sizeof(float) * 1 + 64 * C * sizeof(float); // 96KB: Wp 64KB + Xs 32KB
    smem = (2 * 8192 + 8192) * sizeof(float);
    cudaFuncSetAttribute(k_gemm, cudaFuncAttributeMaxDynamicSharedMemorySize, (int)smem);
    cudaFuncSetAttribute(k_gemm, cudaFuncAttributePreferredSharedMemoryCarveout, 100);

    int initg = (NG * C + 255) / 256;
    if (initg < NBLK) initg = NBLK;

    k_init<<<initg, 256>>>((const int*)ei);                   // 0
    k_convert_hist<<<(NE + 255) / 256, 256>>>(ei, batch);     // 1
    k_scanA<<<NBLK, 256>>>();                                 // 2

    // Layer 1 (gemm only needs x, W1, dis)
    k_gemm<<<(NN + 63) / 64, 256, smem>>>(x, W1, dis, A);     // 3  <- ncu lands here
    k_scanB<<<NBLK, 256>>>();                                 // 4
    k_fill<<<(NE + 255) / 256, 256>>>();                      // 5
    k_agg_relu<<<(NN + 7) / 8, 256>>>(A, b1, X2);             // 6

    // Layer 2
    k_gemm<<<(NN + 63) / 64, 256, smem>>>(X2, W2, dis, A);    // 7
    k_agg_pool<<<(NN + 7) / 8, 256>>>(A, b2);                 // 8

    // Head
    k_fc<<<1, 128>>>(Wfc, bfc, out);                          // 9
}